// round 1
// baseline (speedup 1.0000x reference)
#include <cuda_runtime.h>
#include <cuda_bf16.h>
#include <math.h>

// Problem constants
#define BB   2
#define TT   2048
#define DD   2048
#define HH   16
#define KVH  4
#define HDD  128
#define REPP 4
#define MROWS (BB*TT)          // 4096
#define KVD  (KVH*HDD)          // 512

// Scratch (device globals: no allocation allowed)
__device__ float g_Q[MROWS * DD];     // 32 MB
__device__ float g_K[MROWS * KVD];    // 8 MB
__device__ float g_V[MROWS * KVD];    // 8 MB
__device__ float g_Attn[MROWS * DD];  // 32 MB

// ---------------------------------------------------------------------------
// Generic tiled SGEMM: C[M,N] = A[M,K] * B[K,N], all row-major.
// BM=BN=64, BK=16, 256 threads, 4x4 register tile per thread.
// doRound: apply round-to-4-decimals on store (for final output proj).
// ---------------------------------------------------------------------------
__global__ __launch_bounds__(256) void gemm64_kernel(
    const float* __restrict__ A, const float* __restrict__ B,
    float* __restrict__ C, int M, int N, int K, int doRound)
{
    // padded strides to dodge bank conflicts while keeping 16B alignment
    __shared__ float As[16 * 68];   // As[k][row] (transposed)
    __shared__ float Bs[16 * 68];   // Bs[k][col]

    const int tid = threadIdx.x;
    const int tx = tid & 15;        // 0..15 -> col group
    const int ty = tid >> 4;        // 0..15 -> row group
    const int row0 = blockIdx.y * 64;
    const int col0 = blockIdx.x * 64;

    // A-load mapping: each thread loads one float4 (row r, k kk..kk+3)
    const int ar = tid >> 2;          // 0..63
    const int ak = (tid & 3) * 4;     // 0,4,8,12
    // B-load mapping: each thread loads one float4 (k bk, cols bc..bc+3)
    const int bk = tid >> 4;          // 0..15
    const int bc = (tid & 15) * 4;    // 0..60

    float acc[4][4];
#pragma unroll
    for (int i = 0; i < 4; i++)
#pragma unroll
        for (int j = 0; j < 4; j++) acc[i][j] = 0.f;

    for (int k0 = 0; k0 < K; k0 += 16) {
        float4 a4 = *(const float4*)&A[(size_t)(row0 + ar) * K + k0 + ak];
        As[(ak + 0) * 68 + ar] = a4.x;
        As[(ak + 1) * 68 + ar] = a4.y;
        As[(ak + 2) * 68 + ar] = a4.z;
        As[(ak + 3) * 68 + ar] = a4.w;
        float4 b4 = *(const float4*)&B[(size_t)(k0 + bk) * N + col0 + bc];
        *(float4*)&Bs[bk * 68 + bc] = b4;
        __syncthreads();

#pragma unroll
        for (int kk = 0; kk < 16; kk++) {
            float4 av = *(const float4*)&As[kk * 68 + ty * 4];
            float4 bv = *(const float4*)&Bs[kk * 68 + tx * 4];
            float a[4] = {av.x, av.y, av.z, av.w};
            float b[4] = {bv.x, bv.y, bv.z, bv.w};
#pragma unroll
            for (int i = 0; i < 4; i++)
#pragma unroll
                for (int j = 0; j < 4; j++)
                    acc[i][j] = fmaf(a[i], b[j], acc[i][j]);
        }
        __syncthreads();
    }

#pragma unroll
    for (int i = 0; i < 4; i++) {
        float4 o;
        if (doRound) {
            o.x = rintf(acc[i][0] * 1e4f) * 1e-4f;
            o.y = rintf(acc[i][1] * 1e4f) * 1e-4f;
            o.z = rintf(acc[i][2] * 1e4f) * 1e-4f;
            o.w = rintf(acc[i][3] * 1e4f) * 1e-4f;
        } else {
            o.x = acc[i][0]; o.y = acc[i][1]; o.z = acc[i][2]; o.w = acc[i][3];
        }
        *(float4*)&C[(size_t)(row0 + ty * 4 + i) * N + col0 + tx * 4] = o;
    }
}

// ---------------------------------------------------------------------------
// Flash-attention (causal, GQA). One CTA = 32 query rows of one (b, h).
// BM=BN=32, HD=128, 256 threads.
// Thread layout for accumulation: q = tid/8, dims [(tid%8)*16 .. +15].
// ---------------------------------------------------------------------------
#define QS 132   // padded row stride (floats), 528B: 16B-aligned, bank-shifted
#define SS 33    // padded S stride

__global__ __launch_bounds__(256) void flash_kernel(
    const float* __restrict__ Q, const float* __restrict__ Kb,
    const float* __restrict__ Vb, float* __restrict__ O)
{
    __shared__ float sQ[32 * QS];
    __shared__ float sKV[32 * QS];
    __shared__ float sS[32 * SS];
    __shared__ float sM[32], sL[32], sScale[32];

    const int tid = threadIdx.x;
    const int qb = blockIdx.x;          // query block (0..63)
    const int h  = blockIdx.y;          // 0..15
    const int b  = blockIdx.z;          // 0..1
    const int g  = h / REPP;            // kv head

    const float SM_SCALE = 0.08838834764831845f;  // 1/sqrt(128)

    // Load Q tile (32 rows x 128) into smem
    {
        const size_t base = ((size_t)(b * TT + qb * 32)) * DD + h * HDD;
        for (int f = tid; f < 1024; f += 256) {
            int r = f >> 5, c4 = f & 31;
            float4 v = *(const float4*)&Q[base + (size_t)r * DD + c4 * 4];
            *(float4*)&sQ[r * QS + c4 * 4] = v;
        }
    }
    if (tid < 32) { sM[tid] = -1e30f; sL[tid] = 0.f; }

    const int q  = tid >> 3;            // 0..31 query within tile
    const int d0 = (tid & 7) * 16;      // dim base within head
    const int s0 = (tid & 7) * 4;       // score cols for S compute
    float acc[16];
#pragma unroll
    for (int d = 0; d < 16; d++) acc[d] = 0.f;

    const size_t kvbase = ((size_t)(b * TT)) * KVD + g * HDD;

    for (int jb = 0; jb <= qb; jb++) {
        __syncthreads();   // protect sKV/sS from previous iteration readers

        // Load K tile
        for (int f = tid; f < 1024; f += 256) {
            int r = f >> 5, c4 = f & 31;
            float4 v = *(const float4*)&Kb[kvbase + (size_t)(jb * 32 + r) * KVD + c4 * 4];
            *(float4*)&sKV[r * QS + c4 * 4] = v;
        }
        __syncthreads();

        // S = Q K^T * scale  (each thread: 4 scores for row q)
        {
            const float4* qp = (const float4*)&sQ[q * QS];
            const float4* k0p = (const float4*)&sKV[(s0 + 0) * QS];
            const float4* k1p = (const float4*)&sKV[(s0 + 1) * QS];
            const float4* k2p = (const float4*)&sKV[(s0 + 2) * QS];
            const float4* k3p = (const float4*)&sKV[(s0 + 3) * QS];
            float dot0 = 0.f, dot1 = 0.f, dot2 = 0.f, dot3 = 0.f;
#pragma unroll 8
            for (int t = 0; t < 32; t++) {
                float4 a = qp[t];
                float4 b0 = k0p[t], b1 = k1p[t], b2 = k2p[t], b3 = k3p[t];
                dot0 += a.x*b0.x + a.y*b0.y + a.z*b0.z + a.w*b0.w;
                dot1 += a.x*b1.x + a.y*b1.y + a.z*b1.z + a.w*b1.w;
                dot2 += a.x*b2.x + a.y*b2.y + a.z*b2.z + a.w*b2.w;
                dot3 += a.x*b3.x + a.y*b3.y + a.z*b3.z + a.w*b3.w;
            }
            float sc[4] = {dot0, dot1, dot2, dot3};
#pragma unroll
            for (int i = 0; i < 4; i++) {
                float v = sc[i] * SM_SCALE;
                if (jb == qb && (s0 + i) > q) v = -1e30f;   // causal mask
                sS[q * SS + s0 + i] = v;
            }
        }
        __syncthreads();

        // Load V tile (overwrites sKV; S is already in sS)
        for (int f = tid; f < 1024; f += 256) {
            int r = f >> 5, c4 = f & 31;
            float4 v = *(const float4*)&Vb[kvbase + (size_t)(jb * 32 + r) * KVD + c4 * 4];
            *(float4*)&sKV[r * QS + c4 * 4] = v;
        }
        // Online softmax: one thread per query row
        if (tid < 32) {
            const int qq = tid;
            float m_old = sM[qq];
            float rmax = -1e30f;
#pragma unroll 8
            for (int s = 0; s < 32; s++) rmax = fmaxf(rmax, sS[qq * SS + s]);
            float m_new = fmaxf(m_old, rmax);
            float corr = __expf(m_old - m_new);
            float sum = 0.f;
#pragma unroll 8
            for (int s = 0; s < 32; s++) {
                float p = __expf(sS[qq * SS + s] - m_new);
                sS[qq * SS + s] = p;
                sum += p;
            }
            sM[qq] = m_new;
            sL[qq] = sL[qq] * corr + sum;
            sScale[qq] = corr;
        }
        __syncthreads();

        // O = O*corr + P V
        {
            float corr = sScale[q];
#pragma unroll
            for (int d = 0; d < 16; d++) acc[d] *= corr;
#pragma unroll 4
            for (int s = 0; s < 32; s++) {
                float p = sS[q * SS + s];
                const float4* vp = (const float4*)&sKV[s * QS + d0];
#pragma unroll
                for (int j = 0; j < 4; j++) {
                    float4 v = vp[j];
                    acc[j*4+0] = fmaf(p, v.x, acc[j*4+0]);
                    acc[j*4+1] = fmaf(p, v.y, acc[j*4+1]);
                    acc[j*4+2] = fmaf(p, v.z, acc[j*4+2]);
                    acc[j*4+3] = fmaf(p, v.w, acc[j*4+3]);
                }
            }
        }
    }

    // Epilogue: normalize and store
    {
        float inv = 1.0f / sL[q];
        size_t obase = ((size_t)(b * TT + qb * 32 + q)) * DD + h * HDD + d0;
#pragma unroll
        for (int j = 0; j < 4; j++) {
            float4 o;
            o.x = acc[j*4+0] * inv;
            o.y = acc[j*4+1] * inv;
            o.z = acc[j*4+2] * inv;
            o.w = acc[j*4+3] * inv;
            *(float4*)&O[obase + j * 4] = o;
        }
    }
}

// ---------------------------------------------------------------------------
extern "C" void kernel_launch(void* const* d_in, const int* in_sizes, int n_in,
                              void* d_out, int out_size)
{
    const float* x  = (const float*)d_in[0];
    const float* Wq = (const float*)d_in[1];
    const float* Wk = (const float*)d_in[2];
    const float* Wv = (const float*)d_in[3];
    const float* Wo = (const float*)d_in[4];
    float* out = (float*)d_out;
    (void)in_sizes; (void)n_in; (void)out_size;

    float *Qp, *Kp, *Vp, *Ap;
    cudaGetSymbolAddress((void**)&Qp, g_Q);
    cudaGetSymbolAddress((void**)&Kp, g_K);
    cudaGetSymbolAddress((void**)&Vp, g_V);
    cudaGetSymbolAddress((void**)&Ap, g_Attn);

    // Projections
    gemm64_kernel<<<dim3(DD / 64, MROWS / 64), 256>>>(x, Wq, Qp, MROWS, DD, DD, 0);
    gemm64_kernel<<<dim3(KVD / 64, MROWS / 64), 256>>>(x, Wk, Kp, MROWS, KVD, DD, 0);
    gemm64_kernel<<<dim3(KVD / 64, MROWS / 64), 256>>>(x, Wv, Vp, MROWS, KVD, DD, 0);

    // Attention
    flash_kernel<<<dim3(TT / 32, HH, BB), 256>>>(Qp, Kp, Vp, Ap);

    // Output projection with round-to-4-decimals
    gemm64_kernel<<<dim3(DD / 64, MROWS / 64), 256>>>(Ap, Wo, out, MROWS, DD, DD, 1);
}

// round 3
// speedup vs baseline: 1.1446x; 1.1446x over previous
#include <cuda_runtime.h>
#include <cuda_bf16.h>
#include <stdint.h>
#include <math.h>

// Problem constants
#define BB   2
#define TT   2048
#define DD   2048
#define HH   16
#define KVH  4
#define HDD  128
#define REPP 4
#define MROWS (BB*TT)          // 4096
#define KVD  (KVH*HDD)          // 512

// Scratch (device globals: no allocation allowed)
__device__ float g_Q[MROWS * DD];     // 32 MB
__device__ float g_K[MROWS * KVD];    // 8 MB
__device__ float g_V[MROWS * KVD];    // 8 MB
__device__ float g_Attn[MROWS * DD];  // 32 MB

// ---------------------------------------------------------------------------
// tf32 tensor-core GEMM: C[M,N] = A[M,K] * B[K,N], row-major.
// CTA tile 128x128x32, 256 threads = 8 warps (2x4), warp tile 64x32.
// mma.sync.aligned.m16n8k8 tf32, fp32 accumulate.
// Register-prefetch pipeline to hide global latency.
// ---------------------------------------------------------------------------
__device__ __forceinline__ unsigned int f2tf(float f) {
    unsigned int r;
    asm("cvt.rna.tf32.f32 %0, %1;" : "=r"(r) : "f"(f));
    return r;
}

__device__ __forceinline__ void mma_tf32(float* c,
    unsigned int a0, unsigned int a1, unsigned int a2, unsigned int a3,
    unsigned int b0, unsigned int b1)
{
    asm volatile(
        "mma.sync.aligned.m16n8k8.row.col.f32.tf32.tf32.f32 "
        "{%0,%1,%2,%3}, {%4,%5,%6,%7}, {%8,%9}, {%0,%1,%2,%3};"
        : "+f"(c[0]), "+f"(c[1]), "+f"(c[2]), "+f"(c[3])
        : "r"(a0), "r"(a1), "r"(a2), "r"(a3), "r"(b0), "r"(b1));
}

#define GBM 128
#define GBN 128
#define GBK 32
#define SA_STR 36    // [m][k] stride: (row*36+tig)%32 = row*4+tig -> conflict-free
#define SB_STR 136   // [k][n] stride: (k*136+n)%32 = k*8+n -> conflict-free

__global__ __launch_bounds__(256) void gemm_tf32_kernel(
    const float* __restrict__ A, const float* __restrict__ B,
    float* __restrict__ C, int M, int N, int K, int doRound)
{
    __shared__ unsigned int sA[GBM * SA_STR];   // 18.4 KB
    __shared__ unsigned int sB[GBK * SB_STR];   // 17.4 KB

    const int tid  = threadIdx.x;
    const int lane = tid & 31;
    const int warp = tid >> 5;
    const int gid  = lane >> 2;     // 0..7
    const int tig  = lane & 3;      // 0..3
    const int wm   = (warp >> 2) * 64;   // 0 or 64
    const int wn   = (warp & 3) * 32;    // 0,32,64,96

    const int row0 = blockIdx.y * GBM;
    const int col0 = blockIdx.x * GBN;

    // Global-load mappings (each thread: 16 contiguous floats = 4 float4)
    const int arow = tid >> 1;            // 0..127
    const int akk  = (tid & 1) * 16;      // 0 or 16
    const int brow = tid >> 3;            // 0..31
    const int bnn  = (tid & 7) * 16;      // 0..112

    const float* Ag = A + (size_t)(row0 + arow) * K + akk;
    const float* Bg = B + (size_t)brow * N + col0 + bnn;

    float4 pa[4], pb[4];
    // initial prefetch (k0 = 0)
#pragma unroll
    for (int i = 0; i < 4; i++) pa[i] = *(const float4*)(Ag + i * 4);
#pragma unroll
    for (int i = 0; i < 4; i++) pb[i] = *(const float4*)(Bg + i * 4);

    float acc[4][4][4];
#pragma unroll
    for (int i = 0; i < 4; i++)
#pragma unroll
        for (int j = 0; j < 4; j++)
#pragma unroll
            for (int r = 0; r < 4; r++) acc[i][j][r] = 0.f;

    for (int k0 = 0; k0 < K; k0 += GBK) {
        // store prefetched tile to smem (converted to tf32)
#pragma unroll
        for (int i = 0; i < 4; i++) {
            unsigned int* d = &sA[arow * SA_STR + akk + i * 4];
            d[0] = f2tf(pa[i].x); d[1] = f2tf(pa[i].y);
            d[2] = f2tf(pa[i].z); d[3] = f2tf(pa[i].w);
        }
#pragma unroll
        for (int i = 0; i < 4; i++) {
            unsigned int* d = &sB[brow * SB_STR + bnn + i * 4];
            d[0] = f2tf(pb[i].x); d[1] = f2tf(pb[i].y);
            d[2] = f2tf(pb[i].z); d[3] = f2tf(pb[i].w);
        }
        __syncthreads();

        // prefetch next tile (overlaps with mma compute below)
        if (k0 + GBK < K) {
            const float* An = Ag + k0 + GBK;
            const float* Bn = Bg + (size_t)(k0 + GBK) * N;
#pragma unroll
            for (int i = 0; i < 4; i++) pa[i] = *(const float4*)(An + i * 4);
#pragma unroll
            for (int i = 0; i < 4; i++) pb[i] = *(const float4*)(Bn + i * 4);
        }

        // 4 k-steps of 8
#pragma unroll
        for (int ks = 0; ks < GBK; ks += 8) {
            unsigned int af[4][4], bf[4][2];
#pragma unroll
            for (int i = 0; i < 4; i++) {
                int rb = wm + i * 16 + gid;
                af[i][0] = sA[(rb)     * SA_STR + ks + tig];
                af[i][1] = sA[(rb + 8) * SA_STR + ks + tig];
                af[i][2] = sA[(rb)     * SA_STR + ks + tig + 4];
                af[i][3] = sA[(rb + 8) * SA_STR + ks + tig + 4];
            }
#pragma unroll
            for (int j = 0; j < 4; j++) {
                int cb = wn + j * 8 + gid;
                bf[j][0] = sB[(ks + tig)     * SB_STR + cb];
                bf[j][1] = sB[(ks + tig + 4) * SB_STR + cb];
            }
#pragma unroll
            for (int i = 0; i < 4; i++)
#pragma unroll
                for (int j = 0; j < 4; j++)
                    mma_tf32(acc[i][j], af[i][0], af[i][1], af[i][2], af[i][3],
                             bf[j][0], bf[j][1]);
        }
        __syncthreads();
    }

    // Epilogue: c0,c1 at (row, col*2), c2,c3 at (row+8, col*2)
#pragma unroll
    for (int i = 0; i < 4; i++) {
#pragma unroll
        for (int j = 0; j < 4; j++) {
            int r = row0 + wm + i * 16 + gid;
            int cc = col0 + wn + j * 8 + tig * 2;
            float2 lo, hi;
            if (doRound) {
                lo.x = rintf(acc[i][j][0] * 1e4f) * 1e-4f;
                lo.y = rintf(acc[i][j][1] * 1e4f) * 1e-4f;
                hi.x = rintf(acc[i][j][2] * 1e4f) * 1e-4f;
                hi.y = rintf(acc[i][j][3] * 1e4f) * 1e-4f;
            } else {
                lo.x = acc[i][j][0]; lo.y = acc[i][j][1];
                hi.x = acc[i][j][2]; hi.y = acc[i][j][3];
            }
            *(float2*)&C[(size_t)r * N + cc] = lo;
            *(float2*)&C[(size_t)(r + 8) * N + cc] = hi;
        }
    }
}

// ---------------------------------------------------------------------------
// Flash-attention (causal, GQA). One CTA = 32 query rows of one (b, h).
// BM=BN=32, HD=128, 256 threads.  (unchanged this round)
// ---------------------------------------------------------------------------
#define QS 132
#define SS 33

__global__ __launch_bounds__(256) void flash_kernel(
    const float* __restrict__ Q, const float* __restrict__ Kb,
    const float* __restrict__ Vb, float* __restrict__ O)
{
    __shared__ float sQ[32 * QS];
    __shared__ float sKV[32 * QS];
    __shared__ float sS[32 * SS];
    __shared__ float sM[32], sL[32], sScale[32];

    const int tid = threadIdx.x;
    const int qb = blockIdx.x;
    const int h  = blockIdx.y;
    const int b  = blockIdx.z;
    const int g  = h / REPP;

    const float SM_SCALE = 0.08838834764831845f;

    {
        const size_t base = ((size_t)(b * TT + qb * 32)) * DD + h * HDD;
        for (int f = tid; f < 1024; f += 256) {
            int r = f >> 5, c4 = f & 31;
            float4 v = *(const float4*)&Q[base + (size_t)r * DD + c4 * 4];
            *(float4*)&sQ[r * QS + c4 * 4] = v;
        }
    }
    if (tid < 32) { sM[tid] = -1e30f; sL[tid] = 0.f; }

    const int q  = tid >> 3;
    const int d0 = (tid & 7) * 16;
    const int s0 = (tid & 7) * 4;
    float acc[16];
#pragma unroll
    for (int d = 0; d < 16; d++) acc[d] = 0.f;

    const size_t kvbase = ((size_t)(b * TT)) * KVD + g * HDD;

    for (int jb = 0; jb <= qb; jb++) {
        __syncthreads();

        for (int f = tid; f < 1024; f += 256) {
            int r = f >> 5, c4 = f & 31;
            float4 v = *(const float4*)&Kb[kvbase + (size_t)(jb * 32 + r) * KVD + c4 * 4];
            *(float4*)&sKV[r * QS + c4 * 4] = v;
        }
        __syncthreads();

        {
            const float4* qp = (const float4*)&sQ[q * QS];
            const float4* k0p = (const float4*)&sKV[(s0 + 0) * QS];
            const float4* k1p = (const float4*)&sKV[(s0 + 1) * QS];
            const float4* k2p = (const float4*)&sKV[(s0 + 2) * QS];
            const float4* k3p = (const float4*)&sKV[(s0 + 3) * QS];
            float dot0 = 0.f, dot1 = 0.f, dot2 = 0.f, dot3 = 0.f;
#pragma unroll 8
            for (int t = 0; t < 32; t++) {
                float4 a = qp[t];
                float4 b0 = k0p[t], b1 = k1p[t], b2 = k2p[t], b3 = k3p[t];
                dot0 += a.x*b0.x + a.y*b0.y + a.z*b0.z + a.w*b0.w;
                dot1 += a.x*b1.x + a.y*b1.y + a.z*b1.z + a.w*b1.w;
                dot2 += a.x*b2.x + a.y*b2.y + a.z*b2.z + a.w*b2.w;
                dot3 += a.x*b3.x + a.y*b3.y + a.z*b3.z + a.w*b3.w;
            }
            float sc[4] = {dot0, dot1, dot2, dot3};
#pragma unroll
            for (int i = 0; i < 4; i++) {
                float v = sc[i] * SM_SCALE;
                if (jb == qb && (s0 + i) > q) v = -1e30f;
                sS[q * SS + s0 + i] = v;
            }
        }
        __syncthreads();

        for (int f = tid; f < 1024; f += 256) {
            int r = f >> 5, c4 = f & 31;
            float4 v = *(const float4*)&Vb[kvbase + (size_t)(jb * 32 + r) * KVD + c4 * 4];
            *(float4*)&sKV[r * QS + c4 * 4] = v;
        }
        if (tid < 32) {
            const int qq = tid;
            float m_old = sM[qq];
            float rmax = -1e30f;
#pragma unroll 8
            for (int s = 0; s < 32; s++) rmax = fmaxf(rmax, sS[qq * SS + s]);
            float m_new = fmaxf(m_old, rmax);
            float corr = __expf(m_old - m_new);
            float sum = 0.f;
#pragma unroll 8
            for (int s = 0; s < 32; s++) {
                float p = __expf(sS[qq * SS + s] - m_new);
                sS[qq * SS + s] = p;
                sum += p;
            }
            sM[qq] = m_new;
            sL[qq] = sL[qq] * corr + sum;
            sScale[qq] = corr;
        }
        __syncthreads();

        {
            float corr = sScale[q];
#pragma unroll
            for (int d = 0; d < 16; d++) acc[d] *= corr;
#pragma unroll 4
            for (int s = 0; s < 32; s++) {
                float p = sS[q * SS + s];
                const float4* vp = (const float4*)&sKV[s * QS + d0];
#pragma unroll
                for (int j = 0; j < 4; j++) {
                    float4 v = vp[j];
                    acc[j*4+0] = fmaf(p, v.x, acc[j*4+0]);
                    acc[j*4+1] = fmaf(p, v.y, acc[j*4+1]);
                    acc[j*4+2] = fmaf(p, v.z, acc[j*4+2]);
                    acc[j*4+3] = fmaf(p, v.w, acc[j*4+3]);
                }
            }
        }
    }

    {
        float inv = 1.0f / sL[q];
        size_t obase = ((size_t)(b * TT + qb * 32 + q)) * DD + h * HDD + d0;
#pragma unroll
        for (int j = 0; j < 4; j++) {
            float4 o;
            o.x = acc[j*4+0] * inv;
            o.y = acc[j*4+1] * inv;
            o.z = acc[j*4+2] * inv;
            o.w = acc[j*4+3] * inv;
            *(float4*)&O[obase + j * 4] = o;
        }
    }
}

// ---------------------------------------------------------------------------
extern "C" void kernel_launch(void* const* d_in, const int* in_sizes, int n_in,
                              void* d_out, int out_size)
{
    const float* x  = (const float*)d_in[0];
    const float* Wq = (const float*)d_in[1];
    const float* Wk = (const float*)d_in[2];
    const float* Wv = (const float*)d_in[3];
    const float* Wo = (const float*)d_in[4];
    float* out = (float*)d_out;
    (void)in_sizes; (void)n_in; (void)out_size;

    float *Qp, *Kp, *Vp, *Ap;
    cudaGetSymbolAddress((void**)&Qp, g_Q);
    cudaGetSymbolAddress((void**)&Kp, g_K);
    cudaGetSymbolAddress((void**)&Vp, g_V);
    cudaGetSymbolAddress((void**)&Ap, g_Attn);

    // Projections (tf32 tensor cores)
    gemm_tf32_kernel<<<dim3(DD / GBN, MROWS / GBM), 256>>>(x, Wq, Qp, MROWS, DD, DD, 0);
    gemm_tf32_kernel<<<dim3(KVD / GBN, MROWS / GBM), 256>>>(x, Wk, Kp, MROWS, KVD, DD, 0);
    gemm_tf32_kernel<<<dim3(KVD / GBN, MROWS / GBM), 256>>>(x, Wv, Vp, MROWS, KVD, DD, 0);

    // Attention
    flash_kernel<<<dim3(TT / 32, HH, BB), 256>>>(Qp, Kp, Vp, Ap);

    // Output projection with round-to-4-decimals
    gemm_tf32_kernel<<<dim3(DD / GBN, MROWS / GBM), 256>>>(Ap, Wo, out, MROWS, DD, DD, 1);
}

// round 4
// speedup vs baseline: 7.6256x; 6.6620x over previous
#include <cuda_runtime.h>
#include <cuda_bf16.h>
#include <stdint.h>
#include <math.h>

// Problem constants
#define BB   2
#define TT   2048
#define DD   2048
#define HH   16
#define KVH  4
#define HDD  128
#define REPP 4
#define MROWS (BB*TT)          // 4096
#define KVD  (KVH*HDD)          // 512

// Scratch (device globals: no allocation allowed)
__device__ float g_Q[MROWS * DD];     // 32 MB
__device__ float g_K[MROWS * KVD];    // 8 MB
__device__ float g_V[MROWS * KVD];    // 8 MB
__device__ float g_Attn[MROWS * DD];  // 32 MB

// ---------------------------------------------------------------------------
// Common PTX helpers
// ---------------------------------------------------------------------------
__device__ __forceinline__ unsigned int f2tf(float f) {
    unsigned int r;
    asm("cvt.rna.tf32.f32 %0, %1;" : "=r"(r) : "f"(f));
    return r;
}

__device__ __forceinline__ float ex2(float x) {
    float r;
    asm("ex2.approx.ftz.f32 %0, %1;" : "=f"(r) : "f"(x));
    return r;
}

__device__ __forceinline__ void mma_tf32(float* c,
    unsigned int a0, unsigned int a1, unsigned int a2, unsigned int a3,
    unsigned int b0, unsigned int b1)
{
    asm volatile(
        "mma.sync.aligned.m16n8k8.row.col.f32.tf32.tf32.f32 "
        "{%0,%1,%2,%3}, {%4,%5,%6,%7}, {%8,%9}, {%0,%1,%2,%3};"
        : "+f"(c[0]), "+f"(c[1]), "+f"(c[2]), "+f"(c[3])
        : "r"(a0), "r"(a1), "r"(a2), "r"(a3), "r"(b0), "r"(b1));
}

// ---------------------------------------------------------------------------
// tf32 tensor-core GEMM: C[M,N] = A[M,K] * B[K,N], row-major. (unchanged)
// ---------------------------------------------------------------------------
#define GBM 128
#define GBN 128
#define GBK 32
#define SA_STR 36
#define SB_STR 136

__global__ __launch_bounds__(256) void gemm_tf32_kernel(
    const float* __restrict__ A, const float* __restrict__ B,
    float* __restrict__ C, int M, int N, int K, int doRound)
{
    __shared__ unsigned int sA[GBM * SA_STR];
    __shared__ unsigned int sB[GBK * SB_STR];

    const int tid  = threadIdx.x;
    const int lane = tid & 31;
    const int warp = tid >> 5;
    const int gid  = lane >> 2;
    const int tig  = lane & 3;
    const int wm   = (warp >> 2) * 64;
    const int wn   = (warp & 3) * 32;

    const int row0 = blockIdx.y * GBM;
    const int col0 = blockIdx.x * GBN;

    const int arow = tid >> 1;
    const int akk  = (tid & 1) * 16;
    const int brow = tid >> 3;
    const int bnn  = (tid & 7) * 16;

    const float* Ag = A + (size_t)(row0 + arow) * K + akk;
    const float* Bg = B + (size_t)brow * N + col0 + bnn;

    float4 pa[4], pb[4];
#pragma unroll
    for (int i = 0; i < 4; i++) pa[i] = *(const float4*)(Ag + i * 4);
#pragma unroll
    for (int i = 0; i < 4; i++) pb[i] = *(const float4*)(Bg + i * 4);

    float acc[4][4][4];
#pragma unroll
    for (int i = 0; i < 4; i++)
#pragma unroll
        for (int j = 0; j < 4; j++)
#pragma unroll
            for (int r = 0; r < 4; r++) acc[i][j][r] = 0.f;

    for (int k0 = 0; k0 < K; k0 += GBK) {
#pragma unroll
        for (int i = 0; i < 4; i++) {
            unsigned int* d = &sA[arow * SA_STR + akk + i * 4];
            d[0] = f2tf(pa[i].x); d[1] = f2tf(pa[i].y);
            d[2] = f2tf(pa[i].z); d[3] = f2tf(pa[i].w);
        }
#pragma unroll
        for (int i = 0; i < 4; i++) {
            unsigned int* d = &sB[brow * SB_STR + bnn + i * 4];
            d[0] = f2tf(pb[i].x); d[1] = f2tf(pb[i].y);
            d[2] = f2tf(pb[i].z); d[3] = f2tf(pb[i].w);
        }
        __syncthreads();

        if (k0 + GBK < K) {
            const float* An = Ag + k0 + GBK;
            const float* Bn = Bg + (size_t)(k0 + GBK) * N;
#pragma unroll
            for (int i = 0; i < 4; i++) pa[i] = *(const float4*)(An + i * 4);
#pragma unroll
            for (int i = 0; i < 4; i++) pb[i] = *(const float4*)(Bn + i * 4);
        }

#pragma unroll
        for (int ks = 0; ks < GBK; ks += 8) {
            unsigned int af[4][4], bf[4][2];
#pragma unroll
            for (int i = 0; i < 4; i++) {
                int rb = wm + i * 16 + gid;
                af[i][0] = sA[(rb)     * SA_STR + ks + tig];
                af[i][1] = sA[(rb + 8) * SA_STR + ks + tig];
                af[i][2] = sA[(rb)     * SA_STR + ks + tig + 4];
                af[i][3] = sA[(rb + 8) * SA_STR + ks + tig + 4];
            }
#pragma unroll
            for (int j = 0; j < 4; j++) {
                int cb = wn + j * 8 + gid;
                bf[j][0] = sB[(ks + tig)     * SB_STR + cb];
                bf[j][1] = sB[(ks + tig + 4) * SB_STR + cb];
            }
#pragma unroll
            for (int i = 0; i < 4; i++)
#pragma unroll
                for (int j = 0; j < 4; j++)
                    mma_tf32(acc[i][j], af[i][0], af[i][1], af[i][2], af[i][3],
                             bf[j][0], bf[j][1]);
        }
        __syncthreads();
    }

#pragma unroll
    for (int i = 0; i < 4; i++) {
#pragma unroll
        for (int j = 0; j < 4; j++) {
            int r = row0 + wm + i * 16 + gid;
            int cc = col0 + wn + j * 8 + tig * 2;
            float2 lo, hi;
            if (doRound) {
                lo.x = rintf(acc[i][j][0] * 1e4f) * 1e-4f;
                lo.y = rintf(acc[i][j][1] * 1e4f) * 1e-4f;
                hi.x = rintf(acc[i][j][2] * 1e4f) * 1e-4f;
                hi.y = rintf(acc[i][j][3] * 1e4f) * 1e-4f;
            } else {
                lo.x = acc[i][j][0]; lo.y = acc[i][j][1];
                hi.x = acc[i][j][2]; hi.y = acc[i][j][3];
            }
            *(float2*)&C[(size_t)r * N + cc] = lo;
            *(float2*)&C[(size_t)(r + 8) * N + cc] = hi;
        }
    }
}

// ---------------------------------------------------------------------------
// Tensor-core flash attention (causal, GQA), tf32 mma.
// BM=128 (8 warps x 16 rows), BN=32, HD=128, 256 threads.
// Each warp owns 16 full S-rows -> warp-local softmax (butterfly over 4 lanes).
// ---------------------------------------------------------------------------
#define FBM 128
#define FBN 32
#define FQS 132                  // sQ/sK row stride (banks 4*gid+tig: clean)
#define FVS 136                  // sV row stride (banks 8*tig+gid: clean)
#define FPS 36                   // sP row stride (banks 4*gid+tig: clean)
#define SK_OFF (FBM * FQS)                 // 16896
#define SV_OFF (SK_OFF + FBN * FQS)        // 21120
#define SP_OFF (SV_OFF + FBN * FVS)        // 25472
#define FSMEM_BYTES ((SP_OFF + FBM * FPS) * 4)   // 120320 B

__global__ __launch_bounds__(256, 1) void flash_tc_kernel(
    const float* __restrict__ Q, const float* __restrict__ Kb,
    const float* __restrict__ Vb, float* __restrict__ O)
{
    extern __shared__ unsigned int smem[];
    unsigned int* sQ = smem;
    unsigned int* sK = smem + SK_OFF;
    unsigned int* sV = smem + SV_OFF;
    unsigned int* sP = smem + SP_OFF;

    const int tid  = threadIdx.x;
    const int warp = tid >> 5;
    const int lane = tid & 31;
    const int gid  = lane >> 2;     // 0..7
    const int tig  = lane & 3;      // 0..3
    const int qb   = (int)gridDim.x - 1 - (int)blockIdx.x;  // biggest work first
    const int h    = blockIdx.y;
    const int b    = blockIdx.z;
    const int g    = h >> 2;        // kv head

    const float SM2 = 0.08838834764831845f * 1.44269504088896f; // 1/sqrt(HD)*log2(e)

    // Load Q tile (128 x 128) -> sQ as tf32
    {
        const float* src = Q + ((size_t)(b * TT + qb * FBM)) * DD + h * HDD;
        for (int f = tid; f < FBM * 32; f += 256) {
            int r = f >> 5, c = (f & 31) * 4;
            float4 v = *(const float4*)(src + (size_t)r * DD + c);
            unsigned int* d = &sQ[r * FQS + c];
            d[0] = f2tf(v.x); d[1] = f2tf(v.y); d[2] = f2tf(v.z); d[3] = f2tf(v.w);
        }
    }

    float acc[16][4];
#pragma unroll
    for (int i = 0; i < 16; i++)
#pragma unroll
        for (int j = 0; j < 4; j++) acc[i][j] = 0.f;
    float m0 = -1e30f, m1 = -1e30f, l0 = 0.f, l1 = 0.f;

    const int   qrow0  = qb * FBM + warp * 16;   // warp's first query row
    const size_t kvbase = (size_t)b * TT * KVD + g * HDD;
    const int   nT     = qb * 4 + 4;

    for (int jb = 0; jb < nT; jb++) {
        __syncthreads();
        // Load K and V tiles (32 x 128 each)
        for (int f = tid; f < FBN * 32; f += 256) {
            int r = f >> 5, c = (f & 31) * 4;
            const size_t off = kvbase + (size_t)(jb * FBN + r) * KVD + c;
            float4 kv = *(const float4*)(Kb + off);
            unsigned int* dk = &sK[r * FQS + c];
            dk[0] = f2tf(kv.x); dk[1] = f2tf(kv.y); dk[2] = f2tf(kv.z); dk[3] = f2tf(kv.w);
            float4 vv = *(const float4*)(Vb + off);
            unsigned int* dv = &sV[r * FVS + c];
            dv[0] = f2tf(vv.x); dv[1] = f2tf(vv.y); dv[2] = f2tf(vv.z); dv[3] = f2tf(vv.w);
        }
        __syncthreads();

        if (jb * FBN <= qrow0 + 15) {   // warp has at least one unmasked row
            // ---- S = Q K^T (16 x 32 per warp) ----
            float sc[4][4];
#pragma unroll
            for (int nb = 0; nb < 4; nb++)
#pragma unroll
                for (int j = 0; j < 4; j++) sc[nb][j] = 0.f;

#pragma unroll
            for (int ks = 0; ks < 16; ks++) {
                const int rb = warp * 16 + gid;
                unsigned int a0 = sQ[(rb)     * FQS + ks * 8 + tig];
                unsigned int a1 = sQ[(rb + 8) * FQS + ks * 8 + tig];
                unsigned int a2 = sQ[(rb)     * FQS + ks * 8 + tig + 4];
                unsigned int a3 = sQ[(rb + 8) * FQS + ks * 8 + tig + 4];
#pragma unroll
                for (int nb = 0; nb < 4; nb++) {
                    unsigned int b0 = sK[(nb * 8 + gid) * FQS + ks * 8 + tig];
                    unsigned int b1 = sK[(nb * 8 + gid) * FQS + ks * 8 + tig + 4];
                    mma_tf32(sc[nb], a0, a1, a2, a3, b0, b1);
                }
            }

            // ---- scale + causal mask ----
            const int r0 = qrow0 + gid, r1 = r0 + 8;
#pragma unroll
            for (int nb = 0; nb < 4; nb++) {
                int c0 = jb * FBN + nb * 8 + tig * 2, c1 = c0 + 1;
                sc[nb][0] = (c0 > r0) ? -1e30f : sc[nb][0] * SM2;
                sc[nb][1] = (c1 > r0) ? -1e30f : sc[nb][1] * SM2;
                sc[nb][2] = (c0 > r1) ? -1e30f : sc[nb][2] * SM2;
                sc[nb][3] = (c1 > r1) ? -1e30f : sc[nb][3] * SM2;
            }

            // ---- online softmax (warp-local: 4 lanes per row) ----
            float rx0 = -1e30f, rx1 = -1e30f;
#pragma unroll
            for (int nb = 0; nb < 4; nb++) {
                rx0 = fmaxf(rx0, fmaxf(sc[nb][0], sc[nb][1]));
                rx1 = fmaxf(rx1, fmaxf(sc[nb][2], sc[nb][3]));
            }
            rx0 = fmaxf(rx0, __shfl_xor_sync(0xffffffffu, rx0, 1));
            rx0 = fmaxf(rx0, __shfl_xor_sync(0xffffffffu, rx0, 2));
            rx1 = fmaxf(rx1, __shfl_xor_sync(0xffffffffu, rx1, 1));
            rx1 = fmaxf(rx1, __shfl_xor_sync(0xffffffffu, rx1, 2));

            float mn0 = fmaxf(m0, rx0), mn1 = fmaxf(m1, rx1);
            float cr0 = ex2(m0 - mn0),  cr1 = ex2(m1 - mn1);
            m0 = mn0; m1 = mn1;

            float rs0 = 0.f, rs1 = 0.f;
#pragma unroll
            for (int nb = 0; nb < 4; nb++) {
                sc[nb][0] = ex2(sc[nb][0] - mn0);
                sc[nb][1] = ex2(sc[nb][1] - mn0);
                sc[nb][2] = ex2(sc[nb][2] - mn1);
                sc[nb][3] = ex2(sc[nb][3] - mn1);
                rs0 += sc[nb][0] + sc[nb][1];
                rs1 += sc[nb][2] + sc[nb][3];
            }
            rs0 += __shfl_xor_sync(0xffffffffu, rs0, 1);
            rs0 += __shfl_xor_sync(0xffffffffu, rs0, 2);
            rs1 += __shfl_xor_sync(0xffffffffu, rs1, 1);
            rs1 += __shfl_xor_sync(0xffffffffu, rs1, 2);
            l0 = l0 * cr0 + rs0;
            l1 = l1 * cr1 + rs1;

            // rescale accumulators
#pragma unroll
            for (int i = 0; i < 16; i++) {
                acc[i][0] *= cr0; acc[i][1] *= cr0;
                acc[i][2] *= cr1; acc[i][3] *= cr1;
            }

            // ---- write P (tf32) to smem for A-fragment layout ----
            {
                const int pr0 = warp * 16 + gid, pr1 = pr0 + 8;
#pragma unroll
                for (int nb = 0; nb < 4; nb++) {
                    int c0 = nb * 8 + tig * 2;
                    sP[pr0 * FPS + c0]     = f2tf(sc[nb][0]);
                    sP[pr0 * FPS + c0 + 1] = f2tf(sc[nb][1]);
                    sP[pr1 * FPS + c0]     = f2tf(sc[nb][2]);
                    sP[pr1 * FPS + c0 + 1] = f2tf(sc[nb][3]);
                }
            }
            __syncwarp();

            // ---- O += P V (16 x 128 per warp) ----
#pragma unroll
            for (int ks = 0; ks < 4; ks++) {
                const int pr = warp * 16 + gid;
                unsigned int a0 = sP[(pr)     * FPS + ks * 8 + tig];
                unsigned int a1 = sP[(pr + 8) * FPS + ks * 8 + tig];
                unsigned int a2 = sP[(pr)     * FPS + ks * 8 + tig + 4];
                unsigned int a3 = sP[(pr + 8) * FPS + ks * 8 + tig + 4];
#pragma unroll
                for (int nb2 = 0; nb2 < 16; nb2++) {
                    unsigned int b0 = sV[(ks * 8 + tig)     * FVS + nb2 * 8 + gid];
                    unsigned int b1 = sV[(ks * 8 + tig + 4) * FVS + nb2 * 8 + gid];
                    mma_tf32(acc[nb2], a0, a1, a2, a3, b0, b1);
                }
            }
        }
    }

    // ---- epilogue: normalize and store ----
    {
        float i0 = 1.0f / l0, i1 = 1.0f / l1;
        float* d0 = O + ((size_t)(b * TT + qrow0 + gid))     * DD + h * HDD;
        float* d1 = O + ((size_t)(b * TT + qrow0 + gid + 8)) * DD + h * HDD;
#pragma unroll
        for (int nb2 = 0; nb2 < 16; nb2++) {
            int c = nb2 * 8 + tig * 2;
            float2 v0 = { acc[nb2][0] * i0, acc[nb2][1] * i0 };
            float2 v1 = { acc[nb2][2] * i1, acc[nb2][3] * i1 };
            *(float2*)(d0 + c) = v0;
            *(float2*)(d1 + c) = v1;
        }
    }
}

// ---------------------------------------------------------------------------
extern "C" void kernel_launch(void* const* d_in, const int* in_sizes, int n_in,
                              void* d_out, int out_size)
{
    const float* x  = (const float*)d_in[0];
    const float* Wq = (const float*)d_in[1];
    const float* Wk = (const float*)d_in[2];
    const float* Wv = (const float*)d_in[3];
    const float* Wo = (const float*)d_in[4];
    float* out = (float*)d_out;
    (void)in_sizes; (void)n_in; (void)out_size;

    float *Qp, *Kp, *Vp, *Ap;
    cudaGetSymbolAddress((void**)&Qp, g_Q);
    cudaGetSymbolAddress((void**)&Kp, g_K);
    cudaGetSymbolAddress((void**)&Vp, g_V);
    cudaGetSymbolAddress((void**)&Ap, g_Attn);

    cudaFuncSetAttribute(flash_tc_kernel,
                         cudaFuncAttributeMaxDynamicSharedMemorySize, FSMEM_BYTES);

    // Projections (tf32 tensor cores)
    gemm_tf32_kernel<<<dim3(DD / GBN, MROWS / GBM), 256>>>(x, Wq, Qp, MROWS, DD, DD, 0);
    gemm_tf32_kernel<<<dim3(KVD / GBN, MROWS / GBM), 256>>>(x, Wk, Kp, MROWS, KVD, DD, 0);
    gemm_tf32_kernel<<<dim3(KVD / GBN, MROWS / GBM), 256>>>(x, Wv, Vp, MROWS, KVD, DD, 0);

    // Tensor-core flash attention
    flash_tc_kernel<<<dim3(TT / FBM, HH, BB), 256, FSMEM_BYTES>>>(Qp, Kp, Vp, Ap);

    // Output projection with round-to-4-decimals
    gemm_tf32_kernel<<<dim3(DD / GBN, MROWS / GBM), 256>>>(Ap, Wo, out, MROWS, DD, DD, 1);
}

// round 8
// speedup vs baseline: 10.4755x; 1.3737x over previous
#include <cuda_runtime.h>
#include <cuda_bf16.h>
#include <stdint.h>
#include <math.h>

// Problem constants
#define BB   2
#define TT   2048
#define DD   2048
#define HH   16
#define KVH  4
#define HDD  128
#define REPP 4
#define MROWS (BB*TT)          // 4096
#define KVD  (KVH*HDD)          // 512

// Scratch (device globals: no allocation allowed)
__device__ float g_Q[MROWS * DD];     // 32 MB
__device__ float g_K[MROWS * KVD];    // 8 MB
__device__ float g_V[MROWS * KVD];    // 8 MB
__device__ float g_Attn[MROWS * DD];  // 32 MB

// ---------------------------------------------------------------------------
// PTX helpers
// ---------------------------------------------------------------------------
__device__ __forceinline__ unsigned int f2tf(float f) {
    unsigned int r;
    asm("cvt.rna.tf32.f32 %0, %1;" : "=r"(r) : "f"(f));
    return r;
}

__device__ __forceinline__ float ex2(float x) {
    float r;
    asm("ex2.approx.ftz.f32 %0, %1;" : "=f"(r) : "f"(x));
    return r;
}

__device__ __forceinline__ void mma_tf32(float* c,
    unsigned int a0, unsigned int a1, unsigned int a2, unsigned int a3,
    unsigned int b0, unsigned int b1)
{
    asm volatile(
        "mma.sync.aligned.m16n8k8.row.col.f32.tf32.tf32.f32 "
        "{%0,%1,%2,%3}, {%4,%5,%6,%7}, {%8,%9}, {%0,%1,%2,%3};"
        : "+f"(c[0]), "+f"(c[1]), "+f"(c[2]), "+f"(c[3])
        : "r"(a0), "r"(a1), "r"(a2), "r"(a3), "r"(b0), "r"(b1));
}

__device__ __forceinline__ void cp16(void* smem, const void* gmem) {
    unsigned s = (unsigned)__cvta_generic_to_shared(smem);
    asm volatile("cp.async.cg.shared.global [%0], [%1], 16;" :: "r"(s), "l"(gmem));
}
__device__ __forceinline__ void cp_commit() {
    asm volatile("cp.async.commit_group;");
}
__device__ __forceinline__ void cp_wait1() {
    asm volatile("cp.async.wait_group 1;");
}

// ---------------------------------------------------------------------------
// tf32 GEMM v3: C[M,N] = A[M,K]*B[K,N].  128x128x32 tile, 4 warps (64x64 each),
// 3-stage cp.async pipeline, 1 barrier/iter, cvt at fragment load (RNA).
// ---------------------------------------------------------------------------
#define GSA_STR 36                    // A [m][k] stride: bank 4*gid+tig
#define GSB_STR 132                   // B [k][n] stride: bank 4*tig+gid
#define GS_A (128 * GSA_STR)          // 4608 words / stage
#define GS_B (32 * GSB_STR)           // 4224 words / stage
#define G_STAGE (GS_A + GS_B)         // 8832 words
#define G_SMEM_BYTES (3 * G_STAGE * 4)  // 105984 B

__global__ void __launch_bounds__(128, 2) gemm_tc2(
    const float* __restrict__ A, const float* __restrict__ B,
    float* __restrict__ C, int M, int N, int K, int doRound)
{
    extern __shared__ float gsm[];

    const int tid  = threadIdx.x;
    const int lane = tid & 31;
    const int warp = tid >> 5;
    const int gid  = lane >> 2;
    const int tig  = lane & 3;
    const int wm   = (warp >> 1) * 64;
    const int wn   = (warp & 1) * 64;

    const int row0 = blockIdx.y * 128;
    const int col0 = blockIdx.x * 128;

    // load mappings (coalesced: 4x128B segs for A, 512B for B)
    const int ar = tid >> 3;          // 0..15
    const int ac = (tid & 7) * 4;     // 0..28
    const int bk = tid >> 5;          // 0..3
    const int bn = (tid & 31) * 4;    // 0..124

    const float* Abase = A + (size_t)row0 * K;
    const float* Bbase = B + col0;

    const int nk = K / 32;

    // stage issue helper (inline)
#define G_ISSUE(sidx, k0)                                                    \
    {                                                                        \
        float* sa = gsm + (sidx) * G_STAGE;                                  \
        float* sb = sa + GS_A;                                               \
        _Pragma("unroll")                                                    \
        for (int p = 0; p < 8; p++)                                          \
            cp16(sa + (ar + 16 * p) * GSA_STR + ac,                          \
                 Abase + (size_t)(ar + 16 * p) * K + (k0) + ac);             \
        _Pragma("unroll")                                                    \
        for (int p = 0; p < 8; p++)                                          \
            cp16(sb + (bk + 4 * p) * GSB_STR + bn,                           \
                 Bbase + (size_t)((k0) + bk + 4 * p) * N + bn);              \
    }

    G_ISSUE(0, 0);
    cp_commit();
    G_ISSUE(1, 32);
    cp_commit();

    float acc[4][8][4];
#pragma unroll
    for (int i = 0; i < 4; i++)
#pragma unroll
        for (int j = 0; j < 8; j++)
#pragma unroll
            for (int r = 0; r < 4; r++) acc[i][j][r] = 0.f;

    int cur = 0;
    for (int it = 0; it < nk; it++) {
        cp_wait1();
        __syncthreads();

        // issue stage it+2 (writes stage (it+2)%3, read last at iter it-1: safe)
        if (it + 2 < nk) {
            int s2 = (it + 2) % 3;
            G_ISSUE(s2, (it + 2) * 32);
        }
        cp_commit();

        const float* cA = gsm + cur * G_STAGE;
        const float* cB = cA + GS_A;

#pragma unroll
        for (int ks = 0; ks < 4; ks++) {
            unsigned int af[4][4];
#pragma unroll
            for (int i = 0; i < 4; i++) {
                int rb = wm + i * 16 + gid;
                af[i][0] = f2tf(cA[(rb)     * GSA_STR + ks * 8 + tig]);
                af[i][1] = f2tf(cA[(rb + 8) * GSA_STR + ks * 8 + tig]);
                af[i][2] = f2tf(cA[(rb)     * GSA_STR + ks * 8 + tig + 4]);
                af[i][3] = f2tf(cA[(rb + 8) * GSA_STR + ks * 8 + tig + 4]);
            }
            unsigned int bf[8][2];
#pragma unroll
            for (int j = 0; j < 8; j++) {
                int cb = wn + j * 8 + gid;
                bf[j][0] = f2tf(cB[(ks * 8 + tig)     * GSB_STR + cb]);
                bf[j][1] = f2tf(cB[(ks * 8 + tig + 4) * GSB_STR + cb]);
            }
#pragma unroll
            for (int i = 0; i < 4; i++)
#pragma unroll
                for (int j = 0; j < 8; j++)
                    mma_tf32(acc[i][j], af[i][0], af[i][1], af[i][2], af[i][3],
                             bf[j][0], bf[j][1]);
        }
        cur = (cur + 1) % 3;
    }
#undef G_ISSUE

    // epilogue
#pragma unroll
    for (int i = 0; i < 4; i++) {
#pragma unroll
        for (int j = 0; j < 8; j++) {
            int r  = row0 + wm + i * 16 + gid;
            int cc = col0 + wn + j * 8 + tig * 2;
            float2 lo, hi;
            if (doRound) {
                lo.x = rintf(acc[i][j][0] * 1e4f) * 1e-4f;
                lo.y = rintf(acc[i][j][1] * 1e4f) * 1e-4f;
                hi.x = rintf(acc[i][j][2] * 1e4f) * 1e-4f;
                hi.y = rintf(acc[i][j][3] * 1e4f) * 1e-4f;
            } else {
                lo.x = acc[i][j][0]; lo.y = acc[i][j][1];
                hi.x = acc[i][j][2]; hi.y = acc[i][j][3];
            }
            *(float2*)&C[(size_t)r * N + cc] = lo;
            *(float2*)&C[(size_t)(r + 8) * N + cc] = hi;
        }
    }
}

// ---------------------------------------------------------------------------
// Tensor-core flash attention v2 (causal, GQA), tf32 mma.
// BM=128 (8 warps x 16 rows), BN=32, HD=128, 256 threads.
// Double-buffered K/V + register prefetch: 1 barrier per tile.
// ---------------------------------------------------------------------------
#define FBM 128
#define FBN 32
#define FQS 132                  // sQ/sK row stride
#define FVS 136                  // sV row stride
#define FPS 36                   // sP row stride
#define FQ_W   (FBM * FQS)       // 16896
#define FP_W   (FBM * FPS)       // 4608
#define FK_W   (FBN * FQS)       // 4224
#define FV_W   (FBN * FVS)       // 4352
// layout: sQ | sP | K0 V0 K1 V1
#define FP_OFF  FQ_W
#define FKV0    (FP_OFF + FP_W)
#define FKV_STRIDE (FK_W + FV_W)
#define FSMEM_BYTES ((FKV0 + 2 * FKV_STRIDE) * 4)   // 154624 B

__global__ void __launch_bounds__(256, 1) flash_tc_kernel(
    const float* __restrict__ Q, const float* __restrict__ Kb,
    const float* __restrict__ Vb, float* __restrict__ O)
{
    extern __shared__ unsigned int smem[];
    unsigned int* sQ = smem;
    unsigned int* sP = smem + FP_OFF;

    const int tid  = threadIdx.x;
    const int warp = tid >> 5;
    const int lane = tid & 31;
    const int gid  = lane >> 2;
    const int tig  = lane & 3;
    const int qb   = (int)gridDim.x - 1 - (int)blockIdx.x;  // biggest work first
    const int h    = blockIdx.y;
    const int b    = blockIdx.z;
    const int g    = h >> 2;

    const float SM2 = 0.08838834764831845f * 1.44269504088896f;

    const int lr = tid >> 5;            // kv row base (0..7)
    const int lc = (tid & 31) * 4;      // col within 128

    const size_t kvbase = (size_t)b * TT * KVD + g * HDD;
    const int    nT     = qb * 4 + 4;

    // ---- prologue: load Q tile, load KV tile 0 ----
    {
        const float* src = Q + ((size_t)(b * TT + qb * FBM)) * DD + h * HDD;
        for (int f = tid; f < FBM * 32; f += 256) {
            int r = f >> 5, c = (f & 31) * 4;
            float4 v = *(const float4*)(src + (size_t)r * DD + c);
            unsigned int* d = &sQ[r * FQS + c];
            d[0] = f2tf(v.x); d[1] = f2tf(v.y); d[2] = f2tf(v.z); d[3] = f2tf(v.w);
        }
        unsigned int* sK0 = smem + FKV0;
        unsigned int* sV0 = sK0 + FK_W;
#pragma unroll
        for (int p = 0; p < 4; p++) {
            int r = lr + p * 8;
            size_t off = kvbase + (size_t)r * KVD + lc;
            float4 kv = *(const float4*)(Kb + off);
            float4 vv = *(const float4*)(Vb + off);
            unsigned int* dk = &sK0[r * FQS + lc];
            dk[0] = f2tf(kv.x); dk[1] = f2tf(kv.y); dk[2] = f2tf(kv.z); dk[3] = f2tf(kv.w);
            unsigned int* dv = &sV0[r * FVS + lc];
            dv[0] = f2tf(vv.x); dv[1] = f2tf(vv.y); dv[2] = f2tf(vv.z); dv[3] = f2tf(vv.w);
        }
    }
    __syncthreads();

    float acc[16][4];
#pragma unroll
    for (int i = 0; i < 16; i++)
#pragma unroll
        for (int j = 0; j < 4; j++) acc[i][j] = 0.f;
    float m0 = -1e30f, m1 = -1e30f, l0 = 0.f, l1 = 0.f;

    const int qrow0 = qb * FBM + warp * 16;

    for (int jb = 0; jb < nT; jb++) {
        const bool hasNext = (jb + 1 < nT);
        float4 kr[4], vr[4];
        if (hasNext) {
#pragma unroll
            for (int p = 0; p < 4; p++) {
                int r = lr + p * 8;
                size_t off = kvbase + (size_t)((jb + 1) * FBN + r) * KVD + lc;
                kr[p] = *(const float4*)(Kb + off);
                vr[p] = *(const float4*)(Vb + off);
            }
        }

        unsigned int* sK = smem + FKV0 + (jb & 1) * FKV_STRIDE;
        unsigned int* sV = sK + FK_W;

        if (jb * FBN <= qrow0 + 15) {
            // ---- S = Q K^T ----
            float sc[4][4];
#pragma unroll
            for (int nb = 0; nb < 4; nb++)
#pragma unroll
                for (int j = 0; j < 4; j++) sc[nb][j] = 0.f;

#pragma unroll
            for (int ks = 0; ks < 16; ks++) {
                const int rb = warp * 16 + gid;
                unsigned int a0 = sQ[(rb)     * FQS + ks * 8 + tig];
                unsigned int a1 = sQ[(rb + 8) * FQS + ks * 8 + tig];
                unsigned int a2 = sQ[(rb)     * FQS + ks * 8 + tig + 4];
                unsigned int a3 = sQ[(rb + 8) * FQS + ks * 8 + tig + 4];
#pragma unroll
                for (int nb = 0; nb < 4; nb++) {
                    unsigned int b0 = sK[(nb * 8 + gid) * FQS + ks * 8 + tig];
                    unsigned int b1 = sK[(nb * 8 + gid) * FQS + ks * 8 + tig + 4];
                    mma_tf32(sc[nb], a0, a1, a2, a3, b0, b1);
                }
            }

            // ---- scale + causal mask ----
            const int r0 = qrow0 + gid, r1 = r0 + 8;
#pragma unroll
            for (int nb = 0; nb < 4; nb++) {
                int c0 = jb * FBN + nb * 8 + tig * 2, c1 = c0 + 1;
                sc[nb][0] = (c0 > r0) ? -1e30f : sc[nb][0] * SM2;
                sc[nb][1] = (c1 > r0) ? -1e30f : sc[nb][1] * SM2;
                sc[nb][2] = (c0 > r1) ? -1e30f : sc[nb][2] * SM2;
                sc[nb][3] = (c1 > r1) ? -1e30f : sc[nb][3] * SM2;
            }

            // ---- online softmax (warp-local) ----
            float rx0 = -1e30f, rx1 = -1e30f;
#pragma unroll
            for (int nb = 0; nb < 4; nb++) {
                rx0 = fmaxf(rx0, fmaxf(sc[nb][0], sc[nb][1]));
                rx1 = fmaxf(rx1, fmaxf(sc[nb][2], sc[nb][3]));
            }
            rx0 = fmaxf(rx0, __shfl_xor_sync(0xffffffffu, rx0, 1));
            rx0 = fmaxf(rx0, __shfl_xor_sync(0xffffffffu, rx0, 2));
            rx1 = fmaxf(rx1, __shfl_xor_sync(0xffffffffu, rx1, 1));
            rx1 = fmaxf(rx1, __shfl_xor_sync(0xffffffffu, rx1, 2));

            float mn0 = fmaxf(m0, rx0), mn1 = fmaxf(m1, rx1);
            float cr0 = ex2(m0 - mn0),  cr1 = ex2(m1 - mn1);
            m0 = mn0; m1 = mn1;

            float rs0 = 0.f, rs1 = 0.f;
#pragma unroll
            for (int nb = 0; nb < 4; nb++) {
                sc[nb][0] = ex2(sc[nb][0] - mn0);
                sc[nb][1] = ex2(sc[nb][1] - mn0);
                sc[nb][2] = ex2(sc[nb][2] - mn1);
                sc[nb][3] = ex2(sc[nb][3] - mn1);
                rs0 += sc[nb][0] + sc[nb][1];
                rs1 += sc[nb][2] + sc[nb][3];
            }
            rs0 += __shfl_xor_sync(0xffffffffu, rs0, 1);
            rs0 += __shfl_xor_sync(0xffffffffu, rs0, 2);
            rs1 += __shfl_xor_sync(0xffffffffu, rs1, 1);
            rs1 += __shfl_xor_sync(0xffffffffu, rs1, 2);
            l0 = l0 * cr0 + rs0;
            l1 = l1 * cr1 + rs1;

#pragma unroll
            for (int i = 0; i < 16; i++) {
                acc[i][0] *= cr0; acc[i][1] *= cr0;
                acc[i][2] *= cr1; acc[i][3] *= cr1;
            }

            // ---- write P to smem (A-fragment layout) ----
            {
                const int pr0 = warp * 16 + gid, pr1 = pr0 + 8;
#pragma unroll
                for (int nb = 0; nb < 4; nb++) {
                    int c0 = nb * 8 + tig * 2;
                    sP[pr0 * FPS + c0]     = f2tf(sc[nb][0]);
                    sP[pr0 * FPS + c0 + 1] = f2tf(sc[nb][1]);
                    sP[pr1 * FPS + c0]     = f2tf(sc[nb][2]);
                    sP[pr1 * FPS + c0 + 1] = f2tf(sc[nb][3]);
                }
            }
            __syncwarp();

            // ---- O += P V ----
#pragma unroll
            for (int ks = 0; ks < 4; ks++) {
                const int pr = warp * 16 + gid;
                unsigned int a0 = sP[(pr)     * FPS + ks * 8 + tig];
                unsigned int a1 = sP[(pr + 8) * FPS + ks * 8 + tig];
                unsigned int a2 = sP[(pr)     * FPS + ks * 8 + tig + 4];
                unsigned int a3 = sP[(pr + 8) * FPS + ks * 8 + tig + 4];
#pragma unroll
                for (int nb2 = 0; nb2 < 16; nb2++) {
                    unsigned int b0 = sV[(ks * 8 + tig)     * FVS + nb2 * 8 + gid];
                    unsigned int b1 = sV[(ks * 8 + tig + 4) * FVS + nb2 * 8 + gid];
                    mma_tf32(acc[nb2], a0, a1, a2, a3, b0, b1);
                }
            }
        }

        // ---- store prefetched tile to the other buffer ----
        if (hasNext) {
            unsigned int* nK = smem + FKV0 + ((jb + 1) & 1) * FKV_STRIDE;
            unsigned int* nV = nK + FK_W;
#pragma unroll
            for (int p = 0; p < 4; p++) {
                int r = lr + p * 8;
                unsigned int* dk = &nK[r * FQS + lc];
                dk[0] = f2tf(kr[p].x); dk[1] = f2tf(kr[p].y);
                dk[2] = f2tf(kr[p].z); dk[3] = f2tf(kr[p].w);
                unsigned int* dv = &nV[r * FVS + lc];
                dv[0] = f2tf(vr[p].x); dv[1] = f2tf(vr[p].y);
                dv[2] = f2tf(vr[p].z); dv[3] = f2tf(vr[p].w);
            }
        }
        __syncthreads();
    }

    // ---- epilogue ----
    {
        float i0 = 1.0f / l0, i1 = 1.0f / l1;
        float* d0 = O + ((size_t)(b * TT + qrow0 + gid))     * DD + h * HDD;
        float* d1 = O + ((size_t)(b * TT + qrow0 + gid + 8)) * DD + h * HDD;
#pragma unroll
        for (int nb2 = 0; nb2 < 16; nb2++) {
            int c = nb2 * 8 + tig * 2;
            float2 v0 = { acc[nb2][0] * i0, acc[nb2][1] * i0 };
            float2 v1 = { acc[nb2][2] * i1, acc[nb2][3] * i1 };
            *(float2*)(d0 + c) = v0;
            *(float2*)(d1 + c) = v1;
        }
    }
}

// ---------------------------------------------------------------------------
extern "C" void kernel_launch(void* const* d_in, const int* in_sizes, int n_in,
                              void* d_out, int out_size)
{
    const float* x  = (const float*)d_in[0];
    const float* Wq = (const float*)d_in[1];
    const float* Wk = (const float*)d_in[2];
    const float* Wv = (const float*)d_in[3];
    const float* Wo = (const float*)d_in[4];
    float* out = (float*)d_out;
    (void)in_sizes; (void)n_in; (void)out_size;

    float *Qp, *Kp, *Vp, *Ap;
    cudaGetSymbolAddress((void**)&Qp, g_Q);
    cudaGetSymbolAddress((void**)&Kp, g_K);
    cudaGetSymbolAddress((void**)&Vp, g_V);
    cudaGetSymbolAddress((void**)&Ap, g_Attn);

    cudaFuncSetAttribute(gemm_tc2,
                         cudaFuncAttributeMaxDynamicSharedMemorySize, G_SMEM_BYTES);
    cudaFuncSetAttribute(flash_tc_kernel,
                         cudaFuncAttributeMaxDynamicSharedMemorySize, FSMEM_BYTES);

    // Projections (tf32 tensor cores, pipelined)
    gemm_tc2<<<dim3(DD / 128, MROWS / 128), 128, G_SMEM_BYTES>>>(x, Wq, Qp, MROWS, DD, DD, 0);
    gemm_tc2<<<dim3(KVD / 128, MROWS / 128), 128, G_SMEM_BYTES>>>(x, Wk, Kp, MROWS, KVD, DD, 0);
    gemm_tc2<<<dim3(KVD / 128, MROWS / 128), 128, G_SMEM_BYTES>>>(x, Wv, Vp, MROWS, KVD, DD, 0);

    // Tensor-core flash attention (pipelined)
    flash_tc_kernel<<<dim3(TT / FBM, HH, BB), 256, FSMEM_BYTES>>>(Qp, Kp, Vp, Ap);

    // Output projection with round-to-4-decimals
    gemm_tc2<<<dim3(DD / 128, MROWS / 128), 128, G_SMEM_BYTES>>>(Ap, Wo, out, MROWS, DD, DD, 1);
}